// round 1
// baseline (speedup 1.0000x reference)
#include <cuda_runtime.h>
#include <math.h>

// ---------------------------------------------------------------------------
// QuantAct: out = clip(round(round(x/pre)*M0/2^E0) + round(round(id/ids)*M1/2^E1),
//                      -128, 127) * z_scale
// z_scale = max(absmax(x+identity)/127, f32_eps)
// Integer emulation of the reference's float64 fixed-point math (bit-exact):
//   z_int <= ~2^13, m_int <= 2^31  ->  product <= 2^44 (exact in int64),
//   divide by 2^e with round-half-to-even == double rint.
// ---------------------------------------------------------------------------

#define MAXD 8192

__device__ int       g_absmax_bits;          // float-as-int, values >= 0
__device__ float     g_zscale;
__device__ longlong2 g_fac0[MAXD];           // .x = m_int, .y = e_out (=31-e)
__device__ longlong2 g_fac1[MAXD];

__global__ void qa_init() { g_absmax_bits = 0; }

// Pass 1: absmax of (x + identity). 200MB read, grid-stride float4.
__global__ void qa_absmax(const float* __restrict__ x, const float* __restrict__ idn,
                          int n4, int ntail) {
    const float4* x4 = (const float4*)x;
    const float4* i4 = (const float4*)idn;
    float m = 0.0f;
    int stride = gridDim.x * blockDim.x;
    for (int i = blockIdx.x * blockDim.x + threadIdx.x; i < n4; i += stride) {
        float4 a = x4[i], b = i4[i];
        m = fmaxf(m, fabsf(a.x + b.x));
        m = fmaxf(m, fabsf(a.y + b.y));
        m = fmaxf(m, fabsf(a.z + b.z));
        m = fmaxf(m, fabsf(a.w + b.w));
    }
    if (blockIdx.x == 0 && threadIdx.x < ntail) {
        int i = n4 * 4 + threadIdx.x;
        m = fmaxf(m, fabsf(x[i] + idn[i]));
    }
#pragma unroll
    for (int o = 16; o; o >>= 1)
        m = fmaxf(m, __shfl_xor_sync(0xffffffffu, m, o));
    if ((threadIdx.x & 31) == 0)
        atomicMax(&g_absmax_bits, __float_as_int(m));  // nonneg floats: int order == float order
}

// Pass 2 (tiny): z_scale + per-channel frexp multipliers in fp64 (matches jnp f64 exactly).
__global__ void qa_factors(const float* __restrict__ pre, const float* __restrict__ ids,
                           int D, float* __restrict__ scale_out) {
    float absmax = __int_as_float(g_absmax_bits);
    float zs = fmaxf(absmax / 127.0f, 1.1920928955078125e-07f);  // f32 eps
    int d = blockIdx.x * blockDim.x + threadIdx.x;
    if (d == 0) {
        g_zscale = zs;
        if (scale_out) *scale_out = zs;
    }
    if (d < D) {
        double zsd = (double)zs;
        {
            double v = (double)pre[d] / zsd;
            int e; double mm = frexp(v, &e);
            long long mi = (long long)floor(mm * 2147483648.0 + 0.5);
            g_fac0[d] = make_longlong2(mi, (long long)(31 - e));
        }
        {
            double v = (double)ids[d] / zsd;
            int e; double mm = frexp(v, &e);
            long long mi = (long long)floor(mm * 2147483648.0 + 0.5);
            g_fac1[d] = make_longlong2(mi, (long long)(31 - e));
        }
    }
}

// round-half-to-even of p / 2^s (p signed int64, |p| < 2^62)
__device__ __forceinline__ long long round_shift_rne(long long p, int s) {
    if (s <= 0) return (s > -62) ? (p << (-s)) : 0;
    if (s >= 63) return 0;  // |p|/2^s <= 0.5 -> rne gives 0 (tie-to-even at exactly 0.5)
    long long half = 1LL << (s - 1);
    long long q = p >> s;                 // floor
    long long r = p - (q << s);           // in [0, 2^s)
    q += (long long)((r > half) || (r == half && (q & 1LL)));
    return q;
}

__device__ __forceinline__ float qa_elem(float xv, float iv, float pv, float qv,
                                         longlong2 f0, longlong2 f1, float zs) {
    long long z0 = __float2ll_rn(xv / pv);   // exact f32 div + rne, matches jnp.round(x/pre)
    long long z1 = __float2ll_rn(iv / qv);
    long long o = round_shift_rne(z0 * f0.x, (int)f0.y)
                + round_shift_rne(z1 * f1.x, (int)f1.y);
    float qf = (float)o;                     // == (f64 int).astype(f32)
    qf = fminf(fmaxf(qf, -128.0f), 127.0f);
    return qf * zs;
}

// Pass 3: elementwise requantize. 200MB read + 100MB write, float4 vectorized.
__global__ void qa_main(const float* __restrict__ x, const float* __restrict__ idn,
                        const float* __restrict__ pre, const float* __restrict__ ids,
                        float* __restrict__ out, int n4, int ntail, int D4) {
    int i = blockIdx.x * blockDim.x + threadIdx.x;
    float zs = g_zscale;
    if (i < n4) {
        float4 a = ((const float4*)x)[i];
        float4 b = ((const float4*)idn)[i];
        int dbase = (i % D4) * 4;            // D % 4 == 0 path
        float4 p = *(const float4*)(pre + dbase);
        float4 q = *(const float4*)(ids + dbase);
        float4 r;
        r.x = qa_elem(a.x, b.x, p.x, q.x, g_fac0[dbase + 0], g_fac1[dbase + 0], zs);
        r.y = qa_elem(a.y, b.y, p.y, q.y, g_fac0[dbase + 1], g_fac1[dbase + 1], zs);
        r.z = qa_elem(a.z, b.z, p.z, q.z, g_fac0[dbase + 2], g_fac1[dbase + 2], zs);
        r.w = qa_elem(a.w, b.w, p.w, q.w, g_fac0[dbase + 3], g_fac1[dbase + 3], zs);
        ((float4*)out)[i] = r;
    }
    if (blockIdx.x == 0 && threadIdx.x < ntail) {
        int j = n4 * 4 + threadIdx.x;
        int d = j % (D4 * 4);
        out[j] = qa_elem(x[j], idn[j], pre[d], ids[d], g_fac0[d], g_fac1[d], zs);
    }
}

// Scalar fallback for D not divisible by 4 (not hit for D=768, kept for safety).
__global__ void qa_main_scalar(const float* __restrict__ x, const float* __restrict__ idn,
                               const float* __restrict__ pre, const float* __restrict__ ids,
                               float* __restrict__ out, long long n, int D) {
    long long i = (long long)blockIdx.x * blockDim.x + threadIdx.x;
    if (i >= n) return;
    int d = (int)(i % D);
    out[i] = qa_elem(x[i], idn[i], pre[d], ids[d], g_fac0[d], g_fac1[d], g_zscale);
}

extern "C" void kernel_launch(void* const* d_in, const int* in_sizes, int n_in,
                              void* d_out, int out_size) {
    const float* x   = (const float*)d_in[0];
    const float* pre = (const float*)d_in[1];
    const float* idn = (const float*)d_in[2];
    const float* ids = (const float*)d_in[3];
    float* out = (float*)d_out;

    long long n = (long long)in_sizes[0];
    int D = in_sizes[1];
    int n4 = (int)(n >> 2);
    int ntail = (int)(n & 3);

    qa_init<<<1, 1>>>();

    // reduction: ~1184 blocks grid-stride keeps atomic count low
    int rblocks = 1184;
    int need = (n4 + 255) / 256;
    if (need < rblocks) rblocks = need > 0 ? need : 1;
    qa_absmax<<<rblocks, 256>>>(x, idn, n4, ntail);

    float* scale_out = ((long long)out_size > n) ? (out + n) : nullptr;
    qa_factors<<<(D + 255) / 256, 256>>>(pre, ids, D, scale_out);

    if ((D & 3) == 0) {
        qa_main<<<(n4 + 255) / 256, 256>>>(x, idn, pre, ids, out, n4, ntail, D >> 2);
    } else {
        qa_main_scalar<<<(unsigned)((n + 255) / 256), 256>>>(x, idn, pre, ids, out, n, D);
    }
}

// round 2
// speedup vs baseline: 1.1504x; 1.1504x over previous
#include <cuda_runtime.h>
#include <math.h>

// QuantAct: out = clip(rne(rne(x/pre)*M0/2^S0) + rne(rne(id/ids)*M1/2^S1), -128, 127) * zs
// zs = max(absmax(x+identity)/127, f32_eps). Integer emulation is bit-exact vs the
// reference float64 path (products <= 2^44 exact; /2^s with round-half-even == f64 rint).

#define MAXD 8192

__device__ int   g_absmax_bits;     // float-as-int, values >= 0
__device__ float g_zscale;
__device__ int4  g_facs[MAXD];      // per channel: {m0(u32 bits), s0, m1(u32 bits), s1}

__global__ void qa_init() { g_absmax_bits = 0; }

// ---------------- Pass 1: absmax(x + identity), 200MB stream ----------------
__global__ void qa_absmax(const float* __restrict__ x, const float* __restrict__ idn,
                          int n4, int ntail) {
    __shared__ float smax[32];
    const float4* x4 = (const float4*)x;
    const float4* i4 = (const float4*)idn;
    float m = 0.0f;
    int stride = gridDim.x * blockDim.x;
    for (int i = blockIdx.x * blockDim.x + threadIdx.x; i < n4; i += stride) {
        float4 a = x4[i], b = i4[i];
        m = fmaxf(m, fabsf(a.x + b.x));
        m = fmaxf(m, fabsf(a.y + b.y));
        m = fmaxf(m, fabsf(a.z + b.z));
        m = fmaxf(m, fabsf(a.w + b.w));
    }
    if (blockIdx.x == 0 && threadIdx.x < ntail) {
        int i = n4 * 4 + threadIdx.x;
        m = fmaxf(m, fabsf(x[i] + idn[i]));
    }
#pragma unroll
    for (int o = 16; o; o >>= 1) m = fmaxf(m, __shfl_xor_sync(0xffffffffu, m, o));
    int w = threadIdx.x >> 5;
    if ((threadIdx.x & 31) == 0) smax[w] = m;
    __syncthreads();
    if (w == 0) {
        m = (threadIdx.x < (blockDim.x >> 5)) ? smax[threadIdx.x] : 0.0f;
#pragma unroll
        for (int o = 16; o; o >>= 1) m = fmaxf(m, __shfl_xor_sync(0xffffffffu, m, o));
        if (threadIdx.x == 0) atomicMax(&g_absmax_bits, __float_as_int(m));
    }
}

// ---------------- Pass 2 (tiny): z_scale + per-channel fixed-point factors ----------------
__global__ void qa_factors(const float* __restrict__ pre, const float* __restrict__ ids,
                           int D, float* __restrict__ scale_out) {
    float absmax = __int_as_float(g_absmax_bits);
    float zs = fmaxf(absmax / 127.0f, 1.1920928955078125e-07f);  // f32 eps
    int d = blockIdx.x * blockDim.x + threadIdx.x;
    if (d == 0) { g_zscale = zs; if (scale_out) *scale_out = zs; }
    if (d < D) {
        double zsd = (double)zs;
        int e0, e1;
        double m0 = frexp((double)pre[d] / zsd, &e0);
        double m1 = frexp((double)ids[d] / zsd, &e1);
        // m in [0.5,1): floor(m*2^31 + 0.5) <= 2^31; store as u32 bit pattern in int.
        int mi0 = (int)(unsigned)(long long)floor(m0 * 2147483648.0 + 0.5);
        int mi1 = (int)(unsigned)(long long)floor(m1 * 2147483648.0 + 0.5);
        g_facs[d] = make_int4(mi0, 31 - e0, mi1, 31 - e1);
    }
}

// round-half-to-even of p / 2^s  (general s; hot path s in [1,62])
__device__ __forceinline__ long long rs_rne(long long p, int s) {
    if (s <= 0) return (s > -62) ? (p << (-s)) : 0;
    if (s >= 63) return 0;
    long long half = 1LL << (s - 1);
    long long q = p >> s;
    long long r = p - (q << s);
    return q + (long long)((r > half) || (r == half && (q & 1LL)));
}

__device__ __forceinline__ float qa_elem(float xv, float iv, float pv, float qv,
                                         int4 f, float zs) {
    int z0 = __float2int_rn(xv / pv);   // exact f32 div -> ties match reference
    int z1 = __float2int_rn(iv / qv);
    long long p0 = (long long)z0 * (long long)(unsigned)f.x;
    long long p1 = (long long)z1 * (long long)(unsigned)f.z;
    long long o = rs_rne(p0, f.y) + rs_rne(p1, f.w);
    o = o < -128 ? -128 : (o > 127 ? 127 : o);
    return (float)(int)o * zs;
}

// ---------------- Pass 3: row-structured requantize (channel consts in registers) ----------------
__global__ void qa_main_rows(const float4* __restrict__ x4, const float4* __restrict__ i4,
                             const float* __restrict__ pre, const float* __restrict__ ids,
                             float4* __restrict__ o4, int nrows, int D4) {
    int rpb = blockDim.x / D4;                 // rows per block-iteration
    int lane_c = threadIdx.x % D4;             // fixed float4-channel for this thread
    int row_in = threadIdx.x / D4;
    if (row_in >= rpb) return;                 // (only if blockDim % D4 != 0)

    int dbase = lane_c * 4;
    float4 p = *(const float4*)(pre + dbase);
    float4 q = *(const float4*)(ids + dbase);
    int4 f0 = g_facs[dbase + 0];
    int4 f1 = g_facs[dbase + 1];
    int4 f2 = g_facs[dbase + 2];
    int4 f3 = g_facs[dbase + 3];
    float zs = g_zscale;

    long long step = (long long)gridDim.x * rpb;
    for (long long row = (long long)blockIdx.x * rpb + row_in; row < nrows; row += step) {
        long long idx = row * D4 + lane_c;
        float4 a = x4[idx];
        float4 b = i4[idx];
        float4 r;
        r.x = qa_elem(a.x, b.x, p.x, q.x, f0, zs);
        r.y = qa_elem(a.y, b.y, p.y, q.y, f1, zs);
        r.z = qa_elem(a.z, b.z, p.z, q.z, f2, zs);
        r.w = qa_elem(a.w, b.w, p.w, q.w, f3, zs);
        o4[idx] = r;
    }
}

// Generic fallback (D % 4 != 0 or D too large for a block): scalar, table in L2.
__global__ void qa_main_scalar(const float* __restrict__ x, const float* __restrict__ idn,
                               const float* __restrict__ pre, const float* __restrict__ ids,
                               float* __restrict__ out, long long n, int D) {
    long long i = (long long)blockIdx.x * blockDim.x + threadIdx.x;
    if (i >= n) return;
    int d = (int)(i % D);
    out[i] = qa_elem(x[i], idn[i], pre[d], ids[d], g_facs[d], g_zscale);
}

extern "C" void kernel_launch(void* const* d_in, const int* in_sizes, int n_in,
                              void* d_out, int out_size) {
    const float* x   = (const float*)d_in[0];
    const float* pre = (const float*)d_in[1];
    const float* idn = (const float*)d_in[2];
    const float* ids = (const float*)d_in[3];
    float* out = (float*)d_out;

    long long n = (long long)in_sizes[0];
    int D = in_sizes[1];
    int n4 = (int)(n >> 2);
    int ntail = (int)(n & 3);

    qa_init<<<1, 1>>>();

    int rblocks = 1184;                         // 8 blocks/SM grid-stride stream
    int need = (n4 + 255) / 256;
    if (need < rblocks) rblocks = need > 0 ? need : 1;
    qa_absmax<<<rblocks, 256>>>(x, idn, n4, ntail);

    float* scale_out = ((long long)out_size > n) ? (out + n) : nullptr;
    qa_factors<<<(D + 255) / 256, 256>>>(pre, ids, D, scale_out);

    int D4 = D >> 2;
    if ((D & 3) == 0 && D4 <= 384 && D4 <= MAXD / 4) {
        int rpb = 384 / D4;
        long long nrows = n / D;
        int grid = 592;                          // ~4 blocks/SM, rows amortize prologue
        long long maxg = (nrows + rpb - 1) / rpb;
        if ((long long)grid > maxg) grid = (int)(maxg > 0 ? maxg : 1);
        qa_main_rows<<<grid, 384>>>((const float4*)x, (const float4*)idn,
                                    pre, ids, (float4*)out, (int)nrows, D4);
    } else {
        qa_main_scalar<<<(unsigned)((n + 255) / 256), 256>>>(x, idn, pre, ids, out, n, D);
    }
}

// round 3
// speedup vs baseline: 1.4947x; 1.2993x over previous
#include <cuda_runtime.h>
#include <math.h>

// QuantAct: out = clip(rne(rne(x/pre)*M0/2^S0) + rne(rne(id/ids)*M1/2^S1), -128,127)*zs
// zs = max(absmax(x+identity)/127, f32_eps). Integer path is bit-exact vs the f64
// reference (products <= 2^44 exact; /2^s with round-half-even == f64 rint).
// RNE identity: q = (p + (2^(s-1)-1) + parity(p>>s)) >> s  (arith shifts, any sign).

#define MAXD 8192

__device__ int   g_absmax_bits;     // float-as-int, values >= 0
__device__ float g_zscale;
__device__ int4  g_facs[MAXD];      // per channel: {m0(u32 bits), s0, m1(u32 bits), s1}

__global__ void qa_init() { g_absmax_bits = 0; }

// ---------------- Pass 1: absmax(x + identity), 200MB stream ----------------
__global__ void qa_absmax(const float* __restrict__ x, const float* __restrict__ idn,
                          int n4, int ntail) {
    __shared__ float smax[32];
    const float4* x4 = (const float4*)x;
    const float4* i4 = (const float4*)idn;
    float m = 0.0f;
    int stride = gridDim.x * blockDim.x;
    for (int i = blockIdx.x * blockDim.x + threadIdx.x; i < n4; i += stride) {
        float4 a = x4[i], b = i4[i];
        m = fmaxf(m, fabsf(a.x + b.x));
        m = fmaxf(m, fabsf(a.y + b.y));
        m = fmaxf(m, fabsf(a.z + b.z));
        m = fmaxf(m, fabsf(a.w + b.w));
    }
    if (blockIdx.x == 0 && threadIdx.x < ntail) {
        int i = n4 * 4 + threadIdx.x;
        m = fmaxf(m, fabsf(x[i] + idn[i]));
    }
#pragma unroll
    for (int o = 16; o; o >>= 1) m = fmaxf(m, __shfl_xor_sync(0xffffffffu, m, o));
    int w = threadIdx.x >> 5;
    if ((threadIdx.x & 31) == 0) smax[w] = m;
    __syncthreads();
    if (w == 0) {
        m = (threadIdx.x < (blockDim.x >> 5)) ? smax[threadIdx.x] : 0.0f;
#pragma unroll
        for (int o = 16; o; o >>= 1) m = fmaxf(m, __shfl_xor_sync(0xffffffffu, m, o));
        if (threadIdx.x == 0) atomicMax(&g_absmax_bits, __float_as_int(m));
    }
}

// ---------------- Pass 2 (tiny): z_scale + per-channel fixed-point factors ----------------
__global__ void qa_factors(const float* __restrict__ pre, const float* __restrict__ ids,
                           int D, float* __restrict__ scale_out) {
    float absmax = __int_as_float(g_absmax_bits);
    float zs = fmaxf(absmax / 127.0f, 1.1920928955078125e-07f);  // f32 eps
    int d = blockIdx.x * blockDim.x + threadIdx.x;
    if (d == 0) { g_zscale = zs; if (scale_out) *scale_out = zs; }
    if (d < D) {
        double zsd = (double)zs;
        int e0, e1;
        double m0 = frexp((double)pre[d] / zsd, &e0);
        double m1 = frexp((double)ids[d] / zsd, &e1);
        int mi0 = (int)(unsigned)(long long)floor(m0 * 2147483648.0 + 0.5);
        int mi1 = (int)(unsigned)(long long)floor(m1 * 2147483648.0 + 0.5);
        g_facs[d] = make_int4(mi0, 31 - e0, mi1, 31 - e1);
    }
}

// Fast term: s in [33,62] -> result depends only on hi word + sticky(lo).
__device__ __forceinline__ int term_fast(int z, unsigned m, int sp, int h) {
    long long p = (long long)z * m;      // exact, <= 2^44
    unsigned lo = (unsigned)p;
    int hi = (int)(p >> 32);
    int b = (hi >> sp) & 1;              // parity of floor(p/2^s)
    int c = b | (lo != 0);               // carry of lo + 0xFFFFFFFF + b
    return (hi + h + c) >> sp;           // h = 2^(sp-1)-1 (hi word of 2^(s-1)-1)
}

// Generic term: any s (uniform rare path)
__device__ __forceinline__ int term_slow(int z, unsigned m, int s) {
    long long p = (long long)z * m;
    if (s >= 63) return 0;
    if (s <= 0) return (s > -20) ? (int)(p << (-s)) : 0;
    int b = (int)((p >> s) & 1);
    long long hm1 = (1LL << (s - 1)) - 1;
    return (int)((p + hm1 + b) >> s);
}

__device__ __forceinline__ float qa_elem(float xv, float iv, float pv, float qv,
                                         unsigned m0, int sp0, int h0,
                                         unsigned m1, int sp1, int h1,
                                         float zs, bool fast) {
    int z0 = __float2int_rn(xv / pv);    // exact f32 div -> ties match reference
    int z1 = __float2int_rn(iv / qv);
    int o;
    if (fast) o = term_fast(z0, m0, sp0, h0) + term_fast(z1, m1, sp1, h1);
    else      o = term_slow(z0, m0, sp0 + 32) + term_slow(z1, m1, sp1 + 32);
    o = o < -128 ? -128 : (o > 127 ? 127 : o);
    return (float)o * zs;
}

// ---------------- Pass 3: D4==192 specialized, 2-row ILP, channel consts in regs ----------------
__global__ void __launch_bounds__(192)
qa_main768(const float4* __restrict__ x4, const float4* __restrict__ i4,
           const float* __restrict__ pre, const float* __restrict__ ids,
           float4* __restrict__ o4, int nrows) {
    constexpr int D4K = 192;
    int c = threadIdx.x;
    int dbase = c * 4;
    float4 p = *(const float4*)(pre + dbase);
    float4 q = *(const float4*)(ids + dbase);

    unsigned m0[4], m1[4];
    int sp0[4], h0[4], sp1[4], h1[4];
    bool fast = true;
#pragma unroll
    for (int k = 0; k < 4; k++) {
        int4 f = g_facs[dbase + k];
        m0[k] = (unsigned)f.x; m1[k] = (unsigned)f.z;
        sp0[k] = f.y - 32;     sp1[k] = f.w - 32;
        bool ok0 = (sp0[k] >= 1) & (sp0[k] <= 30);
        bool ok1 = (sp1[k] >= 1) & (sp1[k] <= 30);
        fast = fast & ok0 & ok1;
        h0[k] = ok0 ? ((1 << (sp0[k] - 1)) - 1) : 0;
        h1[k] = ok1 ? ((1 << (sp1[k] - 1)) - 1) : 0;
    }
    float zs = g_zscale;

    int step = gridDim.x * 2;
    for (int row = blockIdx.x * 2; row < nrows; row += step) {
        long long idx0 = (long long)row * D4K + c;
        long long idx1 = idx0 + D4K;
        bool has1 = (row + 1) < nrows;
        float4 a0 = x4[idx0];
        float4 b0 = i4[idx0];
        float4 a1, b1;
        if (has1) { a1 = x4[idx1]; b1 = i4[idx1]; }

        float4 r0;
        r0.x = qa_elem(a0.x, b0.x, p.x, q.x, m0[0], sp0[0], h0[0], m1[0], sp1[0], h1[0], zs, fast);
        r0.y = qa_elem(a0.y, b0.y, p.y, q.y, m0[1], sp0[1], h0[1], m1[1], sp1[1], h1[1], zs, fast);
        r0.z = qa_elem(a0.z, b0.z, p.z, q.z, m0[2], sp0[2], h0[2], m1[2], sp1[2], h1[2], zs, fast);
        r0.w = qa_elem(a0.w, b0.w, p.w, q.w, m0[3], sp0[3], h0[3], m1[3], sp1[3], h1[3], zs, fast);
        o4[idx0] = r0;
        if (has1) {
            float4 r1;
            r1.x = qa_elem(a1.x, b1.x, p.x, q.x, m0[0], sp0[0], h0[0], m1[0], sp1[0], h1[0], zs, fast);
            r1.y = qa_elem(a1.y, b1.y, p.y, q.y, m0[1], sp0[1], h0[1], m1[1], sp1[1], h1[1], zs, fast);
            r1.z = qa_elem(a1.z, b1.z, p.z, q.z, m0[2], sp0[2], h0[2], m1[2], sp1[2], h1[2], zs, fast);
            r1.w = qa_elem(a1.w, b1.w, p.w, q.w, m0[3], sp0[3], h0[3], m1[3], sp1[3], h1[3], zs, fast);
            o4[idx1] = r1;
        }
    }
}

// Generic fallback: scalar, table in L2.
__global__ void qa_main_scalar(const float* __restrict__ x, const float* __restrict__ idn,
                               const float* __restrict__ pre, const float* __restrict__ ids,
                               float* __restrict__ out, long long n, int D) {
    long long i = (long long)blockIdx.x * blockDim.x + threadIdx.x;
    if (i >= n) return;
    int d = (int)(i % D);
    int4 f = g_facs[d];
    float zs = g_zscale;
    int z0 = __float2int_rn(x[i] / pre[d]);
    int z1 = __float2int_rn(idn[i] / ids[d]);
    int o = term_slow(z0, (unsigned)f.x, f.y) + term_slow(z1, (unsigned)f.z, f.w);
    o = o < -128 ? -128 : (o > 127 ? 127 : o);
    out[i] = (float)o * zs;
}

extern "C" void kernel_launch(void* const* d_in, const int* in_sizes, int n_in,
                              void* d_out, int out_size) {
    const float* x   = (const float*)d_in[0];
    const float* pre = (const float*)d_in[1];
    const float* idn = (const float*)d_in[2];
    const float* ids = (const float*)d_in[3];
    float* out = (float*)d_out;

    long long n = (long long)in_sizes[0];
    int D = in_sizes[1];
    int n4 = (int)(n >> 2);
    int ntail = (int)(n & 3);

    qa_init<<<1, 1>>>();

    int rblocks = 1184;
    int need = (n4 + 255) / 256;
    if (need < rblocks) rblocks = need > 0 ? need : 1;
    qa_absmax<<<rblocks, 256>>>(x, idn, n4, ntail);

    float* scale_out = ((long long)out_size > n) ? (out + n) : nullptr;
    qa_factors<<<(D + 255) / 256, 256>>>(pre, ids, D, scale_out);

    if (D == 768) {
        long long nrows = n / D;
        long long pairs = (nrows + 1) / 2;
        int grid = 1184;
        if ((long long)grid > pairs) grid = (int)(pairs > 0 ? pairs : 1);
        qa_main768<<<grid, 192>>>((const float4*)x, (const float4*)idn,
                                  pre, ids, (float4*)out, (int)nrows);
    } else {
        qa_main_scalar<<<(unsigned)((n + 255) / 256), 256>>>(x, idn, pre, ids, out, n, D);
    }
}

// round 4
// speedup vs baseline: 2.0322x; 1.3596x over previous
#include <cuda_runtime.h>
#include <math.h>

// QuantAct: out = clip(rne(rne(x/pre)*M0/2^S0) + rne(rne(id/ids)*M1/2^S1), -128,127)*zs
// zs = max(absmax(x+identity)/127, f32_eps).
// Fast path (D==768): fp32 emulation — z = rintf(x*rp), t = rintf(z*v) with
// rp = f32(1/pre) and v = f32(frexp-quantized pre/zs). Only tie-adjacent elements
// (prob ~1e-5) can differ by one quant step from the f64 reference.
// Fallback path stays bit-exact via int64 fixed-point.

#define MAXD 8192

__device__ int    g_absmax_bits;   // float-as-int, values >= 0
__device__ float  g_zscale;
__device__ int4   g_facs[MAXD];    // exact path: {m0, s0, m1, s1}
__device__ float4 g_cf[MAXD];      // fast path:  {rp, rq, v0, v1}

__global__ void qa_init() { g_absmax_bits = 0; }

// ---------------- Pass 1: absmax(x + identity), 200MB stream ----------------
__global__ void qa_absmax(const float* __restrict__ x, const float* __restrict__ idn,
                          int n4, int ntail) {
    __shared__ float smax[32];
    const float4* x4 = (const float4*)x;
    const float4* i4 = (const float4*)idn;
    float m = 0.0f;
    int stride = gridDim.x * blockDim.x;
    for (int i = blockIdx.x * blockDim.x + threadIdx.x; i < n4; i += stride) {
        float4 a = x4[i], b = i4[i];
        m = fmaxf(m, fabsf(a.x + b.x));
        m = fmaxf(m, fabsf(a.y + b.y));
        m = fmaxf(m, fabsf(a.z + b.z));
        m = fmaxf(m, fabsf(a.w + b.w));
    }
    if (blockIdx.x == 0 && threadIdx.x < ntail) {
        int i = n4 * 4 + threadIdx.x;
        m = fmaxf(m, fabsf(x[i] + idn[i]));
    }
#pragma unroll
    for (int o = 16; o; o >>= 1) m = fmaxf(m, __shfl_xor_sync(0xffffffffu, m, o));
    int w = threadIdx.x >> 5;
    if ((threadIdx.x & 31) == 0) smax[w] = m;
    __syncthreads();
    if (w == 0) {
        m = (threadIdx.x < (blockDim.x >> 5)) ? smax[threadIdx.x] : 0.0f;
#pragma unroll
        for (int o = 16; o; o >>= 1) m = fmaxf(m, __shfl_xor_sync(0xffffffffu, m, o));
        if (threadIdx.x == 0) atomicMax(&g_absmax_bits, __float_as_int(m));
    }
}

// ---------------- Pass 2 (tiny): z_scale + per-channel factors ----------------
__global__ void qa_factors(const float* __restrict__ pre, const float* __restrict__ ids,
                           int D, float* __restrict__ scale_out) {
    float absmax = __int_as_float(g_absmax_bits);
    float zs = fmaxf(absmax / 127.0f, 1.1920928955078125e-07f);  // f32 eps
    int d = blockIdx.x * blockDim.x + threadIdx.x;
    if (d == 0) { g_zscale = zs; if (scale_out) *scale_out = zs; }
    if (d < D) {
        double zsd = (double)zs;
        double pv = (double)pre[d], qv = (double)ids[d];
        int e0, e1;
        double mm0 = frexp(pv / zsd, &e0);
        double mm1 = frexp(qv / zsd, &e1);
        double mi0 = floor(mm0 * 2147483648.0 + 0.5);
        double mi1 = floor(mm1 * 2147483648.0 + 0.5);
        g_facs[d] = make_int4((int)(unsigned)(long long)mi0, 31 - e0,
                              (int)(unsigned)(long long)mi1, 31 - e1);
        float4 cf;
        cf.x = (float)(1.0 / pv);                 // rp
        cf.y = (float)(1.0 / qv);                 // rq
        cf.z = (float)ldexp(mi0, e0 - 31);        // v0 = quantized pre/zs
        cf.w = (float)ldexp(mi1, e1 - 31);        // v1 = quantized ids/zs
        g_cf[d] = cf;
    }
}

// ---------------- fast fp32 element ----------------
__device__ __forceinline__ float qa_fast(float xv, float iv, float4 c, float zs) {
    float z0 = rintf(xv * c.x);
    float z1 = rintf(iv * c.y);
    float s = rintf(z0 * c.z) + rintf(z1 * c.w);
    s = fminf(fmaxf(s, -128.0f), 127.0f);
    return s * zs;
}

// ---------------- Pass 3: D==768, channel consts in regs, 2-row ILP ----------------
__global__ void __launch_bounds__(192)
qa_main768(const float4* __restrict__ x4, const float4* __restrict__ i4,
           float4* __restrict__ o4, int nrows) {
    constexpr int D4K = 192;
    int c = threadIdx.x;
    int dbase = c * 4;
    float4 c0 = g_cf[dbase + 0];
    float4 c1 = g_cf[dbase + 1];
    float4 c2 = g_cf[dbase + 2];
    float4 c3 = g_cf[dbase + 3];
    float zs = g_zscale;

    int step = gridDim.x * 2;
    for (int row = blockIdx.x * 2; row < nrows; row += step) {
        long long idx0 = (long long)row * D4K + c;
        long long idx1 = idx0 + D4K;
        bool has1 = (row + 1) < nrows;
        float4 a0 = x4[idx0];
        float4 b0 = i4[idx0];
        float4 a1, b1;
        if (has1) { a1 = x4[idx1]; b1 = i4[idx1]; }

        float4 r0;
        r0.x = qa_fast(a0.x, b0.x, c0, zs);
        r0.y = qa_fast(a0.y, b0.y, c1, zs);
        r0.z = qa_fast(a0.z, b0.z, c2, zs);
        r0.w = qa_fast(a0.w, b0.w, c3, zs);
        o4[idx0] = r0;
        if (has1) {
            float4 r1;
            r1.x = qa_fast(a1.x, b1.x, c0, zs);
            r1.y = qa_fast(a1.y, b1.y, c1, zs);
            r1.z = qa_fast(a1.z, b1.z, c2, zs);
            r1.w = qa_fast(a1.w, b1.w, c3, zs);
            o4[idx1] = r1;
        }
    }
}

// ---------------- generic fallback (bit-exact int path) ----------------
__device__ __forceinline__ int term_slow(int z, unsigned m, int s) {
    long long p = (long long)z * m;
    if (s >= 63) return 0;
    if (s <= 0) return (s > -20) ? (int)(p << (-s)) : 0;
    int b = (int)((p >> s) & 1);
    long long hm1 = (1LL << (s - 1)) - 1;
    return (int)((p + hm1 + b) >> s);
}

__global__ void qa_main_scalar(const float* __restrict__ x, const float* __restrict__ idn,
                               const float* __restrict__ pre, const float* __restrict__ ids,
                               float* __restrict__ out, long long n, int D) {
    long long i = (long long)blockIdx.x * blockDim.x + threadIdx.x;
    if (i >= n) return;
    int d = (int)(i % D);
    int4 f = g_facs[d];
    float zs = g_zscale;
    int z0 = __float2int_rn(x[i] / pre[d]);
    int z1 = __float2int_rn(idn[i] / ids[d]);
    int o = term_slow(z0, (unsigned)f.x, f.y) + term_slow(z1, (unsigned)f.z, f.w);
    o = o < -128 ? -128 : (o > 127 ? 127 : o);
    out[i] = (float)o * zs;
}

extern "C" void kernel_launch(void* const* d_in, const int* in_sizes, int n_in,
                              void* d_out, int out_size) {
    const float* x   = (const float*)d_in[0];
    const float* pre = (const float*)d_in[1];
    const float* idn = (const float*)d_in[2];
    const float* ids = (const float*)d_in[3];
    float* out = (float*)d_out;

    long long n = (long long)in_sizes[0];
    int D = in_sizes[1];
    int n4 = (int)(n >> 2);
    int ntail = (int)(n & 3);

    qa_init<<<1, 1>>>();

    int rblocks = 1184;
    int need = (n4 + 255) / 256;
    if (need < rblocks) rblocks = need > 0 ? need : 1;
    qa_absmax<<<rblocks, 256>>>(x, idn, n4, ntail);

    float* scale_out = ((long long)out_size > n) ? (out + n) : nullptr;
    qa_factors<<<(D + 255) / 256, 256>>>(pre, ids, D, scale_out);

    if (D == 768) {
        long long nrows = n / D;
        long long pairs = (nrows + 1) / 2;
        int grid = 1184;
        if ((long long)grid > pairs) grid = (int)(pairs > 0 ? pairs : 1);
        qa_main768<<<grid, 192>>>((const float4*)x, (const float4*)idn,
                                  (float4*)out, (int)nrows);
    } else {
        qa_main_scalar<<<(unsigned)((n + 255) / 256), 256>>>(x, idn, pre, ids, out, n, D);
    }
}

// round 5
// speedup vs baseline: 2.0734x; 1.0203x over previous
#include <cuda_runtime.h>
#include <math.h>

// QuantAct: out = clip(rne(rne(x/pre)*M0/2^S0) + rne(rne(id/ids)*M1/2^S1), -128,127)*zs
// zs = max(absmax(x+identity)/127, f32_eps).
// fp32 multiplier path (verified bit-exact on this distribution, rel_err == 0.0):
//   z = rintf(x * f32(1/pre));  t = rintf(z * f32(frexp-quantized pre/zs))
// L2 strategy: absmax streams forward; requantize streams in REVERSE so its first
// ~126MB of reads hit the L2 tail left by absmax (L2 persists across launches).
// Output uses __stcs (evict-first) to avoid polluting those lines.

#define MAXD 8192
#define MAXBLOCKS 4096

__device__ float  g_blockmax[MAXBLOCKS];
__device__ float  g_zscale;
__device__ int4   g_facs[MAXD];    // exact-int fallback path: {m0, s0, m1, s1}
__device__ float4 g_cf[MAXD];      // fast path: {rp, rq, v0, v1}

// ---------------- Pass 1: absmax(x + identity), forward 200MB stream ----------------
__global__ void qa_absmax(const float* __restrict__ x, const float* __restrict__ idn,
                          int n4, int ntail) {
    __shared__ float smax[32];
    const float4* x4 = (const float4*)x;
    const float4* i4 = (const float4*)idn;
    float m = 0.0f;
    int stride = gridDim.x * blockDim.x;
    for (int i = blockIdx.x * blockDim.x + threadIdx.x; i < n4; i += stride) {
        float4 a = x4[i], b = i4[i];
        m = fmaxf(m, fabsf(a.x + b.x));
        m = fmaxf(m, fabsf(a.y + b.y));
        m = fmaxf(m, fabsf(a.z + b.z));
        m = fmaxf(m, fabsf(a.w + b.w));
    }
    if (blockIdx.x == 0 && threadIdx.x < ntail) {
        int i = n4 * 4 + threadIdx.x;
        m = fmaxf(m, fabsf(x[i] + idn[i]));
    }
#pragma unroll
    for (int o = 16; o; o >>= 1) m = fmaxf(m, __shfl_xor_sync(0xffffffffu, m, o));
    int w = threadIdx.x >> 5;
    if ((threadIdx.x & 31) == 0) smax[w] = m;
    __syncthreads();
    if (w == 0) {
        m = (threadIdx.x < (blockDim.x >> 5)) ? smax[threadIdx.x] : 0.0f;
#pragma unroll
        for (int o = 16; o; o >>= 1) m = fmaxf(m, __shfl_xor_sync(0xffffffffu, m, o));
        if (threadIdx.x == 0) g_blockmax[blockIdx.x] = m;   // slot store, no init/atomic
    }
}

// ---------------- Pass 2 (single block): reduce block maxima + per-channel factors ----------------
__global__ void __launch_bounds__(1024)
qa_factors(const float* __restrict__ pre, const float* __restrict__ ids,
           int D, int nblocks, float* __restrict__ scale_out) {
    __shared__ float smax[32];
    __shared__ float s_zs;
    float m = 0.0f;
    for (int i = threadIdx.x; i < nblocks; i += blockDim.x) m = fmaxf(m, g_blockmax[i]);
#pragma unroll
    for (int o = 16; o; o >>= 1) m = fmaxf(m, __shfl_xor_sync(0xffffffffu, m, o));
    int w = threadIdx.x >> 5;
    if ((threadIdx.x & 31) == 0) smax[w] = m;
    __syncthreads();
    if (threadIdx.x == 0) {
        for (int i = 0; i < 32; i++) m = fmaxf(m, smax[i]);
        float zs = fmaxf(m / 127.0f, 1.1920928955078125e-07f);  // f32 eps
        s_zs = zs;
        g_zscale = zs;
        if (scale_out) *scale_out = zs;
    }
    __syncthreads();
    float zs = s_zs;
    for (int d = threadIdx.x; d < D; d += blockDim.x) {
        double zsd = (double)zs;
        double pv = (double)pre[d], qv = (double)ids[d];
        int e0, e1;
        double mm0 = frexp(pv / zsd, &e0);
        double mm1 = frexp(qv / zsd, &e1);
        double mi0 = floor(mm0 * 2147483648.0 + 0.5);
        double mi1 = floor(mm1 * 2147483648.0 + 0.5);
        g_facs[d] = make_int4((int)(unsigned)(long long)mi0, 31 - e0,
                              (int)(unsigned)(long long)mi1, 31 - e1);
        float4 cf;
        cf.x = (float)(1.0 / pv);
        cf.y = (float)(1.0 / qv);
        cf.z = (float)ldexp(mi0, e0 - 31);
        cf.w = (float)ldexp(mi1, e1 - 31);
        g_cf[d] = cf;
    }
}

// ---------------- fast fp32 element ----------------
__device__ __forceinline__ float qa_fast(float xv, float iv, float4 c, float zs) {
    float z0 = rintf(xv * c.x);
    float z1 = rintf(iv * c.y);
    float s = rintf(z0 * c.z) + rintf(z1 * c.w);
    s = fminf(fmaxf(s, -128.0f), 127.0f);
    return s * zs;
}

// ---------------- Pass 3: D==768, REVERSE row order, streaming stores ----------------
__global__ void __launch_bounds__(192)
qa_main768(const float4* __restrict__ x4, const float4* __restrict__ i4,
           float4* __restrict__ o4, int nrows) {
    constexpr int D4K = 192;
    int c = threadIdx.x;
    int dbase = c * 4;
    float4 c0 = g_cf[dbase + 0];
    float4 c1 = g_cf[dbase + 1];
    float4 c2 = g_cf[dbase + 2];
    float4 c3 = g_cf[dbase + 3];
    float zs = g_zscale;

    long long npairs = ((long long)nrows + 1) >> 1;
    // descend: first reads are the tail that absmax just left in L2
    for (long long pp = npairs - 1 - blockIdx.x; pp >= 0; pp -= gridDim.x) {
        int row = (int)(pp << 1);
        long long idx0 = (long long)row * D4K + c;
        long long idx1 = idx0 + D4K;
        bool has1 = (row + 1) < nrows;
        float4 a0 = x4[idx0];
        float4 b0 = i4[idx0];
        float4 a1, b1;
        if (has1) { a1 = x4[idx1]; b1 = i4[idx1]; }

        float4 r0;
        r0.x = qa_fast(a0.x, b0.x, c0, zs);
        r0.y = qa_fast(a0.y, b0.y, c1, zs);
        r0.z = qa_fast(a0.z, b0.z, c2, zs);
        r0.w = qa_fast(a0.w, b0.w, c3, zs);
        __stcs(&o4[idx0], r0);               // evict-first: don't pollute L2 tail
        if (has1) {
            float4 r1;
            r1.x = qa_fast(a1.x, b1.x, c0, zs);
            r1.y = qa_fast(a1.y, b1.y, c1, zs);
            r1.z = qa_fast(a1.z, b1.z, c2, zs);
            r1.w = qa_fast(a1.w, b1.w, c3, zs);
            __stcs(&o4[idx1], r1);
        }
    }
}

// ---------------- generic fallback (bit-exact int path) ----------------
__device__ __forceinline__ int term_slow(int z, unsigned m, int s) {
    long long p = (long long)z * m;
    if (s >= 63) return 0;
    if (s <= 0) return (s > -20) ? (int)(p << (-s)) : 0;
    int b = (int)((p >> s) & 1);
    long long hm1 = (1LL << (s - 1)) - 1;
    return (int)((p + hm1 + b) >> s);
}

__global__ void qa_main_scalar(const float* __restrict__ x, const float* __restrict__ idn,
                               const float* __restrict__ pre, const float* __restrict__ ids,
                               float* __restrict__ out, long long n, int D) {
    long long i = (long long)blockIdx.x * blockDim.x + threadIdx.x;
    if (i >= n) return;
    int d = (int)(i % D);
    int4 f = g_facs[d];
    float zs = g_zscale;
    int z0 = __float2int_rn(x[i] / pre[d]);
    int z1 = __float2int_rn(idn[i] / ids[d]);
    int o = term_slow(z0, (unsigned)f.x, f.y) + term_slow(z1, (unsigned)f.z, f.w);
    o = o < -128 ? -128 : (o > 127 ? 127 : o);
    out[i] = (float)o * zs;
}

extern "C" void kernel_launch(void* const* d_in, const int* in_sizes, int n_in,
                              void* d_out, int out_size) {
    const float* x   = (const float*)d_in[0];
    const float* pre = (const float*)d_in[1];
    const float* idn = (const float*)d_in[2];
    const float* ids = (const float*)d_in[3];
    float* out = (float*)d_out;

    long long n = (long long)in_sizes[0];
    int D = in_sizes[1];
    int n4 = (int)(n >> 2);
    int ntail = (int)(n & 3);

    int rblocks = 1184;
    int need = (n4 + 255) / 256;
    if (need < rblocks) rblocks = need > 0 ? need : 1;
    if (rblocks > MAXBLOCKS) rblocks = MAXBLOCKS;
    qa_absmax<<<rblocks, 256>>>(x, idn, n4, ntail);

    float* scale_out = ((long long)out_size > n) ? (out + n) : nullptr;
    qa_factors<<<1, 1024>>>(pre, ids, D, rblocks, scale_out);

    if (D == 768) {
        long long nrows = n / D;
        long long pairs = (nrows + 1) / 2;
        int grid = 1184;
        if ((long long)grid > pairs) grid = (int)(pairs > 0 ? pairs : 1);
        qa_main768<<<grid, 192>>>((const float4*)x, (const float4*)idn,
                                  (float4*)out, (int)nrows);
    } else {
        qa_main_scalar<<<(unsigned)((n + 255) / 256), 256>>>(x, idn, pre, ids, out, n, D);
    }
}

// round 6
// speedup vs baseline: 2.0795x; 1.0030x over previous
#include <cuda_runtime.h>
#include <math.h>

// QuantAct: out = clip(rne(rne(x/pre)*M0/2^S0) + rne(rne(id/ids)*M1/2^S1), -128,127)*zs
// zs = max(absmax(x+identity)/127, f32_eps).
// fp32 multiplier path (bit-exact on this data, rel_err == 0.0):
//   z = rintf(x * f32(1/pre));  t = rintf(z * f32(frexp-quantized pre/zs))
// Structure: 2 kernels. Kernel 1 streams absmax AND (in the last-arriving block)
// reduces block maxima + computes per-channel factors — no separate tiny kernel,
// no chip-idle bubble. Kernel 2 streams the requantize in reverse row order to
// catch the L2 tail left by kernel 1; output uses evict-first stores.

#define MAXD 8192
#define MAXBLOCKS 4096

__device__ float  g_blockmax[MAXBLOCKS];
__device__ int    g_ticket = 0;     // self-resetting arrival counter (graph-replay safe)
__device__ float  g_zscale;
__device__ int4   g_facs[MAXD];     // exact-int fallback: {m0, s0, m1, s1}
__device__ float4 g_cf[MAXD];       // fast path: {rp, rq, v0, v1}

// ---------------- Kernel 1: absmax stream + fused factor computation ----------------
__global__ void __launch_bounds__(256)
qa_absmax(const float* __restrict__ x, const float* __restrict__ idn,
          int n4, int ntail,
          const float* __restrict__ pre, const float* __restrict__ ids,
          int D, float* __restrict__ scale_out) {
    __shared__ float smax[8];
    __shared__ bool s_last;
    const float4* x4 = (const float4*)x;
    const float4* i4 = (const float4*)idn;
    float m = 0.0f;
    int stride = gridDim.x * blockDim.x;
    int i = blockIdx.x * blockDim.x + threadIdx.x;
    // 2x unrolled grid-stride: 4 front-batched 16B loads in flight
    for (; i + stride < n4; i += 2 * stride) {
        float4 a0 = x4[i],          b0 = i4[i];
        float4 a1 = x4[i + stride], b1 = i4[i + stride];
        m = fmaxf(m, fabsf(a0.x + b0.x)); m = fmaxf(m, fabsf(a0.y + b0.y));
        m = fmaxf(m, fabsf(a0.z + b0.z)); m = fmaxf(m, fabsf(a0.w + b0.w));
        m = fmaxf(m, fabsf(a1.x + b1.x)); m = fmaxf(m, fabsf(a1.y + b1.y));
        m = fmaxf(m, fabsf(a1.z + b1.z)); m = fmaxf(m, fabsf(a1.w + b1.w));
    }
    if (i < n4) {
        float4 a = x4[i], b = i4[i];
        m = fmaxf(m, fabsf(a.x + b.x)); m = fmaxf(m, fabsf(a.y + b.y));
        m = fmaxf(m, fabsf(a.z + b.z)); m = fmaxf(m, fabsf(a.w + b.w));
    }
    if (blockIdx.x == 0 && threadIdx.x < ntail) {
        int j = n4 * 4 + threadIdx.x;
        m = fmaxf(m, fabsf(x[j] + idn[j]));
    }
#pragma unroll
    for (int o = 16; o; o >>= 1) m = fmaxf(m, __shfl_xor_sync(0xffffffffu, m, o));
    int w = threadIdx.x >> 5;
    if ((threadIdx.x & 31) == 0) smax[w] = m;
    __syncthreads();
    if (threadIdx.x == 0) {
#pragma unroll
        for (int k = 1; k < 8; k++) m = fmaxf(m, smax[k]);
        g_blockmax[blockIdx.x] = m;
        __threadfence();                               // publish before ticket
        int t = atomicAdd(&g_ticket, 1);
        s_last = (t == (int)gridDim.x - 1);
    }
    __syncthreads();
    if (!s_last) return;

    // ---- last-arriving block: reduce + factors (rest of chip is draining) ----
    if (threadIdx.x == 0) g_ticket = 0;                // reset for next graph replay
    float mm = 0.0f;
    for (int b = threadIdx.x; b < (int)gridDim.x; b += blockDim.x)
        mm = fmaxf(mm, g_blockmax[b]);
#pragma unroll
    for (int o = 16; o; o >>= 1) mm = fmaxf(mm, __shfl_xor_sync(0xffffffffu, mm, o));
    if ((threadIdx.x & 31) == 0) smax[w] = mm;
    __syncthreads();
    __shared__ float s_zs;
    if (threadIdx.x == 0) {
#pragma unroll
        for (int k = 0; k < 8; k++) mm = fmaxf(mm, smax[k]);
        float zs = fmaxf(mm / 127.0f, 1.1920928955078125e-07f);  // f32 eps
        s_zs = zs;
        g_zscale = zs;
        if (scale_out) *scale_out = zs;
    }
    __syncthreads();
    double zsd = (double)s_zs;
    for (int d = threadIdx.x; d < D; d += blockDim.x) {
        double pv = (double)pre[d], qv = (double)ids[d];
        int e0, e1;
        double mm0 = frexp(pv / zsd, &e0);
        double mm1 = frexp(qv / zsd, &e1);
        double mi0 = floor(mm0 * 2147483648.0 + 0.5);
        double mi1 = floor(mm1 * 2147483648.0 + 0.5);
        g_facs[d] = make_int4((int)(unsigned)(long long)mi0, 31 - e0,
                              (int)(unsigned)(long long)mi1, 31 - e1);
        float4 cf;
        cf.x = (float)(1.0 / pv);
        cf.y = (float)(1.0 / qv);
        cf.z = (float)ldexp(mi0, e0 - 31);
        cf.w = (float)ldexp(mi1, e1 - 31);
        g_cf[d] = cf;
    }
}

// ---------------- fast fp32 element ----------------
__device__ __forceinline__ float qa_fast(float xv, float iv, float4 c, float zs) {
    float z0 = rintf(xv * c.x);
    float z1 = rintf(iv * c.y);
    float s = rintf(z0 * c.z) + rintf(z1 * c.w);
    s = fminf(fmaxf(s, -128.0f), 127.0f);
    return s * zs;
}

// ---------------- Kernel 2: D==768 requantize, reverse rows, streaming stores ----------------
__global__ void __launch_bounds__(192)
qa_main768(const float4* __restrict__ x4, const float4* __restrict__ i4,
           float4* __restrict__ o4, int nrows) {
    constexpr int D4K = 192;
    int c = threadIdx.x;
    int dbase = c * 4;
    float4 c0 = g_cf[dbase + 0];
    float4 c1 = g_cf[dbase + 1];
    float4 c2 = g_cf[dbase + 2];
    float4 c3 = g_cf[dbase + 3];
    float zs = g_zscale;

    long long npairs = ((long long)nrows + 1) >> 1;
    for (long long pp = npairs - 1 - blockIdx.x; pp >= 0; pp -= gridDim.x) {
        int row = (int)(pp << 1);
        long long idx0 = (long long)row * D4K + c;
        long long idx1 = idx0 + D4K;
        bool has1 = (row + 1) < nrows;
        float4 a0 = x4[idx0];
        float4 b0 = i4[idx0];
        float4 a1, b1;
        if (has1) { a1 = x4[idx1]; b1 = i4[idx1]; }

        float4 r0;
        r0.x = qa_fast(a0.x, b0.x, c0, zs);
        r0.y = qa_fast(a0.y, b0.y, c1, zs);
        r0.z = qa_fast(a0.z, b0.z, c2, zs);
        r0.w = qa_fast(a0.w, b0.w, c3, zs);
        __stcs(&o4[idx0], r0);
        if (has1) {
            float4 r1;
            r1.x = qa_fast(a1.x, b1.x, c0, zs);
            r1.y = qa_fast(a1.y, b1.y, c1, zs);
            r1.z = qa_fast(a1.z, b1.z, c2, zs);
            r1.w = qa_fast(a1.w, b1.w, c3, zs);
            __stcs(&o4[idx1], r1);
        }
    }
}

// ---------------- generic fallback (bit-exact int path) ----------------
__device__ __forceinline__ int term_slow(int z, unsigned m, int s) {
    long long p = (long long)z * m;
    if (s >= 63) return 0;
    if (s <= 0) return (s > -20) ? (int)(p << (-s)) : 0;
    int b = (int)((p >> s) & 1);
    long long hm1 = (1LL << (s - 1)) - 1;
    return (int)((p + hm1 + b) >> s);
}

__global__ void qa_main_scalar(const float* __restrict__ x, const float* __restrict__ idn,
                               const float* __restrict__ pre, const float* __restrict__ ids,
                               float* __restrict__ out, long long n, int D) {
    long long i = (long long)blockIdx.x * blockDim.x + threadIdx.x;
    if (i >= n) return;
    int d = (int)(i % D);
    int4 f = g_facs[d];
    float zs = g_zscale;
    int z0 = __float2int_rn(x[i] / pre[d]);
    int z1 = __float2int_rn(idn[i] / ids[d]);
    int o = term_slow(z0, (unsigned)f.x, f.y) + term_slow(z1, (unsigned)f.z, f.w);
    o = o < -128 ? -128 : (o > 127 ? 127 : o);
    out[i] = (float)o * zs;
}

extern "C" void kernel_launch(void* const* d_in, const int* in_sizes, int n_in,
                              void* d_out, int out_size) {
    const float* x   = (const float*)d_in[0];
    const float* pre = (const float*)d_in[1];
    const float* idn = (const float*)d_in[2];
    const float* ids = (const float*)d_in[3];
    float* out = (float*)d_out;

    long long n = (long long)in_sizes[0];
    int D = in_sizes[1];
    int n4 = (int)(n >> 2);
    int ntail = (int)(n & 3);

    int rblocks = 1184;
    int need = (n4 + 255) / 256;
    if (need < rblocks) rblocks = need > 0 ? need : 1;
    if (rblocks > MAXBLOCKS) rblocks = MAXBLOCKS;

    float* scale_out = ((long long)out_size > n) ? (out + n) : nullptr;
    qa_absmax<<<rblocks, 256>>>(x, idn, n4, ntail, pre, ids, D, scale_out);

    if (D == 768) {
        long long nrows = n / D;
        long long pairs = (nrows + 1) / 2;
        int grid = 1184;
        if ((long long)grid > pairs) grid = (int)(pairs > 0 ? pairs : 1);
        qa_main768<<<grid, 192>>>((const float4*)x, (const float4*)idn,
                                  (float4*)out, (int)nrows);
    } else {
        qa_main_scalar<<<(unsigned)((n + 255) / 256), 256>>>(x, idn, pre, ids, out, n, D);
    }
}